// round 1
// baseline (speedup 1.0000x reference)
#include <cuda_runtime.h>
#include <cuda_bf16.h>

// Problem constants
#define B_   256
#define T_   512
#define I_   256
#define H_   128
#define O_   1000
#define M_   (B_ * T_)      // 131072 rows of the input GEMM

// ---------------------------------------------------------------------------
// Scratch (static __device__ arrays: allocation-guard safe)
// ---------------------------------------------------------------------------
__device__ float g_xp[(size_t)M_ * H_];   // 64 MB: xp[b,t,j] = x@W_ih^T + b_ih + b_hh
__device__ float g_h[B_ * H_];            // final hidden state

// ---------------------------------------------------------------------------
// Kernel 1: xp = x @ W_ih^T + (b_ih + b_hh)
// M=131072, N=128, K=256.  BM=128, BN=128, BK=16, 256 threads, 8x8/thread
// ---------------------------------------------------------------------------
__global__ void __launch_bounds__(256) xp_gemm_kernel(
    const float* __restrict__ X,      // [M_, I_]
    const float* __restrict__ Wih,    // [H_, I_]
    const float* __restrict__ b_ih,   // [H_]
    const float* __restrict__ b_hh)   // [H_]
{
    __shared__ float As[16][132];   // [k][m], padded
    __shared__ float Bs[16][132];   // [k][j], padded

    const int tid  = threadIdx.x;
    const int lrow = tid >> 2;        // 0..63
    const int lseg = tid & 3;         // 0..3  -> k window seg*4
    const int ty   = tid >> 4;        // 0..15
    const int tx   = tid & 15;        // 0..15

    const long mBase = (long)blockIdx.x * 128;
    const float* Xbase = X + mBase * I_;

    float acc[8][8];
#pragma unroll
    for (int i = 0; i < 8; i++)
#pragma unroll
        for (int j = 0; j < 8; j++) acc[i][j] = 0.f;

    for (int k0 = 0; k0 < I_; k0 += 16) {
        float4 a0 = *(const float4*)(Xbase + (long)lrow * I_        + k0 + lseg * 4);
        float4 a1 = *(const float4*)(Xbase + (long)(lrow + 64) * I_ + k0 + lseg * 4);
        float4 b0 = *(const float4*)(Wih + lrow * I_        + k0 + lseg * 4);
        float4 b1 = *(const float4*)(Wih + (lrow + 64) * I_ + k0 + lseg * 4);

        __syncthreads();  // previous compute done before overwriting smem
        As[lseg * 4 + 0][lrow] = a0.x;  As[lseg * 4 + 1][lrow] = a0.y;
        As[lseg * 4 + 2][lrow] = a0.z;  As[lseg * 4 + 3][lrow] = a0.w;
        As[lseg * 4 + 0][lrow + 64] = a1.x;  As[lseg * 4 + 1][lrow + 64] = a1.y;
        As[lseg * 4 + 2][lrow + 64] = a1.z;  As[lseg * 4 + 3][lrow + 64] = a1.w;
        Bs[lseg * 4 + 0][lrow] = b0.x;  Bs[lseg * 4 + 1][lrow] = b0.y;
        Bs[lseg * 4 + 2][lrow] = b0.z;  Bs[lseg * 4 + 3][lrow] = b0.w;
        Bs[lseg * 4 + 0][lrow + 64] = b1.x;  Bs[lseg * 4 + 1][lrow + 64] = b1.y;
        Bs[lseg * 4 + 2][lrow + 64] = b1.z;  Bs[lseg * 4 + 3][lrow + 64] = b1.w;
        __syncthreads();

#pragma unroll
        for (int kk = 0; kk < 16; kk++) {
            float4 av0 = *(const float4*)&As[kk][ty * 4];
            float4 av1 = *(const float4*)&As[kk][64 + ty * 4];
            float4 bv0 = *(const float4*)&Bs[kk][tx * 4];
            float4 bv1 = *(const float4*)&Bs[kk][64 + tx * 4];
            float a[8] = {av0.x, av0.y, av0.z, av0.w, av1.x, av1.y, av1.z, av1.w};
            float b[8] = {bv0.x, bv0.y, bv0.z, bv0.w, bv1.x, bv1.y, bv1.z, bv1.w};
#pragma unroll
            for (int i = 0; i < 8; i++)
#pragma unroll
                for (int j = 0; j < 8; j++)
                    acc[i][j] = fmaf(a[i], b[j], acc[i][j]);
        }
    }

    // epilogue: add bias, store float4
    float biasv[8];
#pragma unroll
    for (int j = 0; j < 8; j++) {
        int col = (j < 4) ? (tx * 4 + j) : (64 + tx * 4 + (j - 4));
        biasv[j] = b_ih[col] + b_hh[col];
    }
#pragma unroll
    for (int i = 0; i < 8; i++) {
        long row = mBase + ((i < 4) ? (ty * 4 + i) : (64 + ty * 4 + (i - 4)));
        float4 v0 = make_float4(acc[i][0] + biasv[0], acc[i][1] + biasv[1],
                                acc[i][2] + biasv[2], acc[i][3] + biasv[3]);
        float4 v1 = make_float4(acc[i][4] + biasv[4], acc[i][5] + biasv[5],
                                acc[i][6] + biasv[6], acc[i][7] + biasv[7]);
        *(float4*)&g_xp[row * H_ + tx * 4]      = v0;
        *(float4*)&g_xp[row * H_ + 64 + tx * 4] = v1;
    }
}

// ---------------------------------------------------------------------------
// Kernel 2: sequential recurrence. One CTA per batch row, 128 threads.
// Thread j holds W_hh[j][0..127] in registers; h in double-buffered SMEM.
// ---------------------------------------------------------------------------
__global__ void __launch_bounds__(128) rnn_scan_kernel(
    const float* __restrict__ Whh)    // [H_, H_]
{
    const int b = blockIdx.x;
    const int j = threadIdx.x;

    __shared__ float hs[2][H_];

    // Load W_hh row j into registers (L2-resident after first wave)
    float w[H_];
    const float4* wrow = (const float4*)(Whh + j * H_);
#pragma unroll
    for (int q = 0; q < H_ / 4; q++) {
        float4 v = wrow[q];
        w[4 * q + 0] = v.x; w[4 * q + 1] = v.y;
        w[4 * q + 2] = v.z; w[4 * q + 3] = v.w;
    }

    hs[0][j] = 0.f;
    __syncthreads();

    const float* xprow = g_xp + ((long)b * T_) * H_ + j;
    float xv = xprow[0];
    float hn = 0.f;
    int cur = 0;

    for (int t = 0; t < T_; t++) {
        // prefetch next timestep's xp early (hidden behind the dot product)
        float xn = (t < T_ - 1) ? xprow[(long)(t + 1) * H_] : 0.f;

        float a0 = 0.f, a1 = 0.f, a2 = 0.f, a3 = 0.f;
#pragma unroll
        for (int k = 0; k < H_; k += 4) {
            float4 h4 = *(const float4*)&hs[cur][k];   // broadcast LDS.128
            a0 = fmaf(h4.x, w[k + 0], a0);
            a1 = fmaf(h4.y, w[k + 1], a1);
            a2 = fmaf(h4.z, w[k + 2], a2);
            a3 = fmaf(h4.w, w[k + 3], a3);
        }
        hn = tanhf(xv + (a0 + a1) + (a2 + a3));
        hs[cur ^ 1][j] = hn;
        __syncthreads();
        xv = xn;
        cur ^= 1;
    }

    g_h[b * H_ + j] = hn;
}

// ---------------------------------------------------------------------------
// Kernel 3: out = h_last @ W_fc^T + b_fc.   grid (16 o-chunks x 8 b-chunks)
// ---------------------------------------------------------------------------
__global__ void __launch_bounds__(256) fc_kernel(
    const float* __restrict__ Wfc,    // [O_, H_]
    const float* __restrict__ bfc,    // [O_]
    float* __restrict__ out)          // [B_, O_]
{
    __shared__ float Ws[64][129];     // padded: conflict-free scalar reads
    __shared__ float Hs[32][128];

    const int tid = threadIdx.x;
    const int oc = blockIdx.x * 64;
    const int bc = blockIdx.y * 32;

    for (int idx = tid; idx < 64 * 128; idx += 256) {
        int r = idx >> 7, c = idx & 127;
        Ws[r][c] = (oc + r < O_) ? Wfc[(oc + r) * H_ + c] : 0.f;
    }
    for (int idx = tid; idx < 32 * 128; idx += 256) {
        int r = idx >> 7, c = idx & 127;
        Hs[r][c] = g_h[(bc + r) * H_ + c];
    }
    __syncthreads();

    const int o_loc = tid & 63;
    const int bg    = tid >> 6;        // 0..3, each handles 8 batch rows
    const int o     = oc + o_loc;
    const float bias = (o < O_) ? bfc[o] : 0.f;

    float accv[8];
#pragma unroll
    for (int bi = 0; bi < 8; bi++) accv[bi] = bias;

#pragma unroll 4
    for (int k = 0; k < H_; k++) {
        float wv = Ws[o_loc][k];
#pragma unroll
        for (int bi = 0; bi < 8; bi++)
            accv[bi] = fmaf(Hs[bg * 8 + bi][k], wv, accv[bi]);
    }

    if (o < O_) {
#pragma unroll
        for (int bi = 0; bi < 8; bi++)
            out[(long)(bc + bg * 8 + bi) * O_ + o] = accv[bi];
    }
}

// ---------------------------------------------------------------------------
// Launch
// ---------------------------------------------------------------------------
extern "C" void kernel_launch(void* const* d_in, const int* in_sizes, int n_in,
                              void* d_out, int out_size)
{
    const float* x    = (const float*)d_in[0];   // [256,512,256]
    const float* Wih  = (const float*)d_in[1];   // [128,256]
    const float* Whh  = (const float*)d_in[2];   // [128,128]
    const float* b_ih = (const float*)d_in[3];   // [128]
    const float* b_hh = (const float*)d_in[4];   // [128]
    const float* Wfc  = (const float*)d_in[5];   // [1000,128]
    const float* bfc  = (const float*)d_in[6];   // [1000]
    float* out = (float*)d_out;                  // [256,1000]

    xp_gemm_kernel<<<M_ / 128, 256>>>(x, Wih, b_ih, b_hh);
    rnn_scan_kernel<<<B_, 128>>>(Whh);
    fc_kernel<<<dim3((O_ + 63) / 64, B_ / 32), 256>>>(Wfc, bfc, out);
}

// round 2
// speedup vs baseline: 1.2211x; 1.2211x over previous
#include <cuda_runtime.h>
#include <cuda_bf16.h>

// Problem constants
#define B_   256
#define T_   512
#define I_   256
#define H_   128
#define O_   1000
#define M_   (B_ * T_)      // 131072 rows of the input GEMM

// ---------------------------------------------------------------------------
// Scratch (static __device__ arrays: allocation-guard safe)
// ---------------------------------------------------------------------------
__device__ float g_xp[(size_t)M_ * H_];   // 64 MB: xp[b,t,j] = x@W_ih^T + b_ih + b_hh
__device__ float g_h[B_ * H_];            // final hidden state

// ---------------------------------------------------------------------------
// Packed f32x2 helpers (sm_10x: fma.rn.f32x2 on 64-bit register pairs)
// ---------------------------------------------------------------------------
__device__ __forceinline__ unsigned long long pack2(float lo, float hi) {
    unsigned long long r;
    asm("mov.b64 %0, {%1, %2};" : "=l"(r) : "f"(lo), "f"(hi));
    return r;
}
__device__ __forceinline__ void fma2(unsigned long long& d,
                                     unsigned long long a,
                                     unsigned long long b) {
    asm("fma.rn.f32x2 %0, %1, %2, %0;" : "+l"(d) : "l"(a), "l"(b));
}
__device__ __forceinline__ float2 unpack2(unsigned long long v) {
    float2 f;
    asm("mov.b64 {%0, %1}, %2;" : "=f"(f.x), "=f"(f.y) : "l"(v));
    return f;
}

// Fast tanh with ~2e-7 abs error: tanh(x) = 1 - 2/(exp2(2x*log2e)+1).
// ex2.approx / rcp.approx have ~2^-22 rel error; saturates correctly at +-1.
__device__ __forceinline__ float fast_tanh(float x) {
    float e;
    asm("ex2.approx.f32 %0, %1;" : "=f"(e) : "f"(x * 2.8853900817779268f));
    float r;
    asm("rcp.approx.f32 %0, %1;" : "=f"(r) : "f"(e + 1.0f));
    return 1.0f - 2.0f * r;
}

// ---------------------------------------------------------------------------
// Kernel 1: xp = x @ W_ih^T + (b_ih + b_hh)
// M=131072, N=128, K=256.  BM=128, BN=128, BK=16, 256 threads, 8x8/thread,
// inner product issued as packed f32x2 FMAs (32 packed vs 64 scalar).
// ---------------------------------------------------------------------------
__global__ void __launch_bounds__(256) xp_gemm_kernel(
    const float* __restrict__ X,      // [M_, I_]
    const float* __restrict__ Wih,    // [H_, I_]
    const float* __restrict__ b_ih,   // [H_]
    const float* __restrict__ b_hh)   // [H_]
{
    __shared__ float As[16][132];   // [k][m], padded
    __shared__ float Bs[16][132];   // [k][j], padded

    const int tid  = threadIdx.x;
    const int lrow = tid >> 2;        // 0..63
    const int lseg = tid & 3;         // 0..3  -> k window seg*4
    const int ty   = tid >> 4;        // 0..15
    const int tx   = tid & 15;        // 0..15

    const long mBase = (long)blockIdx.x * 128;
    const float* Xbase = X + mBase * I_;

    unsigned long long acc2[8][4];    // 8 rows x 4 column-pairs (8 cols)
#pragma unroll
    for (int i = 0; i < 8; i++)
#pragma unroll
        for (int j = 0; j < 4; j++) acc2[i][j] = 0ull;   // (0.f, 0.f)

    for (int k0 = 0; k0 < I_; k0 += 16) {
        float4 a0 = *(const float4*)(Xbase + (long)lrow * I_        + k0 + lseg * 4);
        float4 a1 = *(const float4*)(Xbase + (long)(lrow + 64) * I_ + k0 + lseg * 4);
        float4 b0 = *(const float4*)(Wih + lrow * I_        + k0 + lseg * 4);
        float4 b1 = *(const float4*)(Wih + (lrow + 64) * I_ + k0 + lseg * 4);

        __syncthreads();  // previous compute done before overwriting smem
        As[lseg * 4 + 0][lrow] = a0.x;  As[lseg * 4 + 1][lrow] = a0.y;
        As[lseg * 4 + 2][lrow] = a0.z;  As[lseg * 4 + 3][lrow] = a0.w;
        As[lseg * 4 + 0][lrow + 64] = a1.x;  As[lseg * 4 + 1][lrow + 64] = a1.y;
        As[lseg * 4 + 2][lrow + 64] = a1.z;  As[lseg * 4 + 3][lrow + 64] = a1.w;
        Bs[lseg * 4 + 0][lrow] = b0.x;  Bs[lseg * 4 + 1][lrow] = b0.y;
        Bs[lseg * 4 + 2][lrow] = b0.z;  Bs[lseg * 4 + 3][lrow] = b0.w;
        Bs[lseg * 4 + 0][lrow + 64] = b1.x;  Bs[lseg * 4 + 1][lrow + 64] = b1.y;
        Bs[lseg * 4 + 2][lrow + 64] = b1.z;  Bs[lseg * 4 + 3][lrow + 64] = b1.w;
        __syncthreads();

#pragma unroll
        for (int kk = 0; kk < 16; kk++) {
            float4  av0 = *(const float4*)&As[kk][ty * 4];
            float4  av1 = *(const float4*)&As[kk][64 + ty * 4];
            // B columns as packed pairs straight out of shared (16B aligned)
            double2 bv0 = *(const double2*)&Bs[kk][tx * 4];
            double2 bv1 = *(const double2*)&Bs[kk][64 + tx * 4];
            unsigned long long bp[4] = {
                __double_as_longlong(bv0.x), __double_as_longlong(bv0.y),
                __double_as_longlong(bv1.x), __double_as_longlong(bv1.y)
            };
            float a[8] = {av0.x, av0.y, av0.z, av0.w, av1.x, av1.y, av1.z, av1.w};
#pragma unroll
            for (int i = 0; i < 8; i++) {
                unsigned long long ai = pack2(a[i], a[i]);
                fma2(acc2[i][0], ai, bp[0]);
                fma2(acc2[i][1], ai, bp[1]);
                fma2(acc2[i][2], ai, bp[2]);
                fma2(acc2[i][3], ai, bp[3]);
            }
        }
    }

    // epilogue: add bias, store float4
    float biasv[8];
#pragma unroll
    for (int j = 0; j < 8; j++) {
        int col = (j < 4) ? (tx * 4 + j) : (64 + tx * 4 + (j - 4));
        biasv[j] = b_ih[col] + b_hh[col];
    }
#pragma unroll
    for (int i = 0; i < 8; i++) {
        long row = mBase + ((i < 4) ? (ty * 4 + i) : (64 + ty * 4 + (i - 4)));
        float2 c0 = unpack2(acc2[i][0]);
        float2 c1 = unpack2(acc2[i][1]);
        float2 c2 = unpack2(acc2[i][2]);
        float2 c3 = unpack2(acc2[i][3]);
        float4 v0 = make_float4(c0.x + biasv[0], c0.y + biasv[1],
                                c1.x + biasv[2], c1.y + biasv[3]);
        float4 v1 = make_float4(c2.x + biasv[4], c2.y + biasv[5],
                                c3.x + biasv[6], c3.y + biasv[7]);
        *(float4*)&g_xp[row * H_ + tx * 4]      = v0;
        *(float4*)&g_xp[row * H_ + 64 + tx * 4] = v1;
    }
}

// ---------------------------------------------------------------------------
// Kernel 2: sequential recurrence.
// 128 CTAs x 256 threads; each CTA owns TWO batch rows (one per thread half),
// so every SM holds exactly one CTA (128 < 148: no 2-CTA pacing imbalance).
// Thread (half, j) holds W_hh[j][:] as 64 packed f32x2 registers; h lives in
// double-buffered SMEM read via 16B broadcast loads. xp prefetch distance 2.
// ---------------------------------------------------------------------------
__global__ void __launch_bounds__(256) rnn_scan_kernel(
    const float* __restrict__ Whh)    // [H_, H_]
{
    const int tid  = threadIdx.x;
    const int half = tid >> 7;        // 0/1: which batch row of this CTA
    const int j    = tid & 127;
    const int b    = blockIdx.x * 2 + half;

    __shared__ float hs[2][2][H_];    // [buf][half][j]

    // W_hh row j -> 64 packed f32x2 registers (16B global loads)
    unsigned long long w2[64];
    const ulonglong2* wrow = (const ulonglong2*)(Whh + j * H_);
#pragma unroll
    for (int q = 0; q < 32; q++) {
        ulonglong2 v = wrow[q];
        w2[2 * q + 0] = v.x;
        w2[2 * q + 1] = v.y;
    }

    hs[0][half][j] = 0.f;
    __syncthreads();

    const float* xprow = g_xp + ((long)b * T_) * H_ + j;
    float xb0 = xprow[0];
    float xb1 = xprow[H_];
    float hn  = 0.f;
    int   cur = 0;

    for (int t = 0; t < T_; t++) {
        // prefetch 2 steps ahead: covers DRAM/L2 latency (> one step's work)
        float xn2 = (t + 2 < T_) ? xprow[(size_t)(t + 2) * H_] : 0.f;

        unsigned long long acc0 = 0ull, acc1 = 0ull;
        const double2* hp = (const double2*)hs[cur][half];
#pragma unroll
        for (int k = 0; k < 32; k++) {
            double2 h2 = hp[k];                       // 4 h values, broadcast LDS.128
            fma2(acc0, __double_as_longlong(h2.x), w2[2 * k + 0]);
            fma2(acc1, __double_as_longlong(h2.y), w2[2 * k + 1]);
        }
        float2 s0 = unpack2(acc0);
        float2 s1 = unpack2(acc1);
        hn = fast_tanh(xb0 + (s0.x + s0.y) + (s1.x + s1.y));
        hs[cur ^ 1][half][j] = hn;
        __syncthreads();

        xb0 = xb1;
        xb1 = xn2;
        cur ^= 1;
    }

    g_h[b * H_ + j] = hn;
}

// ---------------------------------------------------------------------------
// Kernel 3: out = h_last @ W_fc^T + b_fc.   grid (16 o-chunks x 8 b-chunks)
// ---------------------------------------------------------------------------
__global__ void __launch_bounds__(256) fc_kernel(
    const float* __restrict__ Wfc,    // [O_, H_]
    const float* __restrict__ bfc,    // [O_]
    float* __restrict__ out)          // [B_, O_]
{
    __shared__ float Ws[64][129];     // padded: conflict-free scalar reads
    __shared__ float Hs[32][128];

    const int tid = threadIdx.x;
    const int oc = blockIdx.x * 64;
    const int bc = blockIdx.y * 32;

    for (int idx = tid; idx < 64 * 128; idx += 256) {
        int r = idx >> 7, c = idx & 127;
        Ws[r][c] = (oc + r < O_) ? Wfc[(oc + r) * H_ + c] : 0.f;
    }
    for (int idx = tid; idx < 32 * 128; idx += 256) {
        int r = idx >> 7, c = idx & 127;
        Hs[r][c] = g_h[(bc + r) * H_ + c];
    }
    __syncthreads();

    const int o_loc = tid & 63;
    const int bg    = tid >> 6;        // 0..3, each handles 8 batch rows
    const int o     = oc + o_loc;
    const float bias = (o < O_) ? bfc[o] : 0.f;

    float accv[8];
#pragma unroll
    for (int bi = 0; bi < 8; bi++) accv[bi] = bias;

#pragma unroll 4
    for (int k = 0; k < H_; k++) {
        float wv = Ws[o_loc][k];
#pragma unroll
        for (int bi = 0; bi < 8; bi++)
            accv[bi] = fmaf(Hs[bg * 8 + bi][k], wv, accv[bi]);
    }

    if (o < O_) {
#pragma unroll
        for (int bi = 0; bi < 8; bi++)
            out[(long)(bc + bg * 8 + bi) * O_ + o] = accv[bi];
    }
}

// ---------------------------------------------------------------------------
// Launch
// ---------------------------------------------------------------------------
extern "C" void kernel_launch(void* const* d_in, const int* in_sizes, int n_in,
                              void* d_out, int out_size)
{
    const float* x    = (const float*)d_in[0];   // [256,512,256]
    const float* Wih  = (const float*)d_in[1];   // [128,256]
    const float* Whh  = (const float*)d_in[2];   // [128,128]
    const float* b_ih = (const float*)d_in[3];   // [128]
    const float* b_hh = (const float*)d_in[4];   // [128]
    const float* Wfc  = (const float*)d_in[5];   // [1000,128]
    const float* bfc  = (const float*)d_in[6];   // [1000]
    float* out = (float*)d_out;                  // [256,1000]

    xp_gemm_kernel<<<M_ / 128, 256>>>(x, Wih, b_ih, b_hh);
    rnn_scan_kernel<<<B_ / 2, 256>>>(Whh);
    fc_kernel<<<dim3((O_ + 63) / 64, B_ / 32), 256>>>(Wfc, bfc, out);
}